// round 1
// baseline (speedup 1.0000x reference)
#include <cuda_runtime.h>
#include <cstdint>

#define BATCH 2
#define CH    256
#define RCH   64
#define NPIX  9216
#define KSEL  16

#define TQ  64
#define TK  128
#define SQS 68    // q tile row stride (floats), 272B = 16B-aligned
#define SKS 132   // k tile row stride (floats), 528B = 16B-aligned
#define SSS 129   // sim tile row stride: odd -> conflict-free owner scan

// scratch (device globals; no allocation allowed)
__device__ float g_nf [BATCH * NPIX * RCH];   // [b*N + n][r]
__device__ float g_nfT[BATCH * RCH * NPIX];   // [b][r][n]
__device__ int   g_topidx[BATCH * NPIX * KSEL];

union F2U { unsigned long long u; float2 f; };

// packed fp32x2 FMA (Blackwell f32x2 pipe, 2x FFMA throughput)
#define FMA2(d, a, b) asm("fma.rn.f32x2 %0, %1, %2, %0;" : "+l"(d) : "l"(a), "l"(b))

// ---------------------------------------------------------------------------
// K1: feat = w_reduce @ x  (per pixel), L2-normalize over rc, write nf & nfT
// ---------------------------------------------------------------------------
__global__ __launch_bounds__(256) void k1_reduce_norm(
    const float* __restrict__ x, const float* __restrict__ w_reduce)
{
    extern __shared__ float smw[];  // [c][r] with stride 68 (transposed w_reduce)
    const int tid = threadIdx.x;

    for (int i = tid; i < CH * RCH; i += 256) {
        int r = i / CH, c = i % CH;          // coalesced read of w_reduce[r][c]
        smw[c * SQS + r] = w_reduce[i];
    }
    __syncthreads();

    const int p = blockIdx.x * 256 + tid;    // global pixel id, 0..18431
    const int b = p / NPIX;
    const int n = p % NPIX;

    float feat[RCH];
#pragma unroll
    for (int r = 0; r < RCH; r++) feat[r] = 0.f;

    const float* xp = x + (size_t)b * CH * NPIX + n;
    for (int c = 0; c < CH; c++) {
        float xv = xp[(size_t)c * NPIX];     // coalesced across threads
        const float4* wrow = reinterpret_cast<const float4*>(&smw[c * SQS]);
#pragma unroll
        for (int r4 = 0; r4 < RCH / 4; r4++) {
            float4 wv = wrow[r4];            // broadcast LDS
            feat[r4 * 4 + 0] += wv.x * xv;
            feat[r4 * 4 + 1] += wv.y * xv;
            feat[r4 * 4 + 2] += wv.z * xv;
            feat[r4 * 4 + 3] += wv.w * xv;
        }
    }
    float ss = 0.f;
#pragma unroll
    for (int r = 0; r < RCH; r++) ss += feat[r] * feat[r];
    float inv = 1.f / fmaxf(sqrtf(ss), 1e-12f);

    float* nfp = g_nf + (size_t)p * RCH;
#pragma unroll
    for (int r4 = 0; r4 < RCH / 4; r4++) {
        float4 v;
        v.x = feat[r4 * 4 + 0] * inv;
        v.y = feat[r4 * 4 + 1] * inv;
        v.z = feat[r4 * 4 + 2] * inv;
        v.w = feat[r4 * 4 + 3] * inv;
        reinterpret_cast<float4*>(nfp)[r4] = v;
    }
    float* nft = g_nfT + (size_t)b * RCH * NPIX + n;
#pragma unroll
    for (int r = 0; r < RCH; r++)
        nft[(size_t)r * NPIX] = feat[r] * inv;   // coalesced across threads
}

// ---------------------------------------------------------------------------
// K2: fused sim-GEMM (f32x2 packed FFMA) + streaming top-16 per query row
// block: 64 query rows, loops 72 tiles of 128 keys. 256 threads (16x16),
// each thread computes a 4(q) x 8(k) register tile.
// ---------------------------------------------------------------------------
__global__ __launch_bounds__(256, 2) void k2_sim_topk()
{
    extern __shared__ float sm[];
    float* sq   = sm;                       // [64][SQS]  q transposed [r][q]
    float* sk   = sq + TQ * SQS;            // [64][SKS]  k transposed [r][k]
    float* ssim = sk + RCH * SKS;           // [64][SSS]
    float* tval = ssim + TQ * SSS;          // [64][16]
    int*   tidx = reinterpret_cast<int*>(tval + TQ * KSEL);  // [64][16]

    const int tid = threadIdx.x;
    const int b   = blockIdx.y;
    const int q0  = blockIdx.x * TQ;
    const int tx  = tid & 15;
    const int ty  = tid >> 4;

    // load query tile (transposed layout already in g_nfT)
    for (int i = tid; i < RCH * TQ; i += 256) {
        int r = i >> 6, q = i & 63;
        sq[r * SQS + q] = g_nfT[((size_t)b * RCH + r) * NPIX + q0 + q];
    }
    if (tid < TQ) {
#pragma unroll
        for (int j = 0; j < KSEL; j++) { tval[tid * KSEL + j] = -3.4e38f; tidx[tid * KSEL + j] = 0; }
    }
    __syncthreads();

    for (int kt = 0; kt < NPIX / TK; kt++) {
        const int k0 = kt * TK;
        // load key tile
        for (int i = tid; i < RCH * TK; i += 256) {
            int r = i >> 7, k = i & 127;
            sk[r * SKS + k] = g_nfT[((size_t)b * RCH + r) * NPIX + k0 + k];
        }
        __syncthreads();

        // GEMM: acc[4][4] of packed float2 (8 k-columns)
        unsigned long long acc[4][4];
#pragma unroll
        for (int i = 0; i < 4; i++)
#pragma unroll
            for (int j = 0; j < 4; j++) acc[i][j] = 0ull;

#pragma unroll 8
        for (int r = 0; r < RCH; r++) {
            const float4 av = *reinterpret_cast<const float4*>(&sq[r * SQS + (ty << 2)]);
            const ulonglong2 b0 = *reinterpret_cast<const ulonglong2*>(&sk[r * SKS + (tx << 3)]);
            const ulonglong2 b1 = *reinterpret_cast<const ulonglong2*>(&sk[r * SKS + (tx << 3) + 4]);
            unsigned long long ad0, ad1, ad2, ad3;
            { F2U t; t.f.x = av.x; t.f.y = av.x; ad0 = t.u; }
            { F2U t; t.f.x = av.y; t.f.y = av.y; ad1 = t.u; }
            { F2U t; t.f.x = av.z; t.f.y = av.z; ad2 = t.u; }
            { F2U t; t.f.x = av.w; t.f.y = av.w; ad3 = t.u; }
            FMA2(acc[0][0], ad0, b0.x); FMA2(acc[0][1], ad0, b0.y);
            FMA2(acc[0][2], ad0, b1.x); FMA2(acc[0][3], ad0, b1.y);
            FMA2(acc[1][0], ad1, b0.x); FMA2(acc[1][1], ad1, b0.y);
            FMA2(acc[1][2], ad1, b1.x); FMA2(acc[1][3], ad1, b1.y);
            FMA2(acc[2][0], ad2, b0.x); FMA2(acc[2][1], ad2, b0.y);
            FMA2(acc[2][2], ad2, b1.x); FMA2(acc[2][3], ad2, b1.y);
            FMA2(acc[3][0], ad3, b0.x); FMA2(acc[3][1], ad3, b0.y);
            FMA2(acc[3][2], ad3, b1.x); FMA2(acc[3][3], ad3, b1.y);
        }

        // dump sim tile to smem
#pragma unroll
        for (int i = 0; i < 4; i++) {
            float* sr = &ssim[((ty << 2) + i) * SSS + (tx << 3)];
#pragma unroll
            for (int jp = 0; jp < 4; jp++) {
                F2U t; t.u = acc[i][jp];
                sr[jp * 2 + 0] = t.f.x;
                sr[jp * 2 + 1] = t.f.y;
            }
        }
        __syncthreads();

        // owner threads: threshold-gated stable insertion into sorted top-16
        if (tid < TQ) {
            float* tv = &tval[tid * KSEL];
            int*   ti = &tidx[tid * KSEL];
            float  thr = tv[KSEL - 1];
            const float* srow = &ssim[tid * SSS];
            for (int p = 0; p < TK; p++) {
                float v = srow[p];
                if (v > thr) {
                    int j = KSEL - 1;
                    while (j > 0 && tv[j - 1] < v) {   // strict: stable ties (lower index wins)
                        tv[j] = tv[j - 1]; ti[j] = ti[j - 1]; j--;
                    }
                    tv[j] = v; ti[j] = k0 + p;
                    thr = tv[KSEL - 1];
                }
            }
        }
        __syncthreads();
    }

    if (tid < TQ) {
        int* dst = &g_topidx[(size_t)(b * NPIX + q0 + tid) * KSEL];
#pragma unroll
        for (int j = 0; j < KSEL; j++) dst[j] = tidx[tid * KSEL + j];
    }
}

// ---------------------------------------------------------------------------
// K3: corr = mean of 16 gathered nf rows; out = x + w_proj @ corr
// ---------------------------------------------------------------------------
__global__ __launch_bounds__(256) void k3_gather_proj(
    const float* __restrict__ x, const float* __restrict__ w_proj,
    float* __restrict__ out)
{
    extern __shared__ float sm[];
    float* swp   = sm;                       // [256][64] w_proj (same layout as global)
    float* scorr = swp + CH * RCH;           // [64][SQS]
    int*   sidx  = reinterpret_cast<int*>(scorr + 64 * SQS);  // [64][16]

    const int tid = threadIdx.x;
    const int b   = blockIdx.y;
    const int n0  = blockIdx.x * 64;

    for (int i = tid; i < CH * RCH; i += 256) swp[i] = w_proj[i];
    for (int i = tid; i < 64 * KSEL; i += 256)
        sidx[i] = g_topidx[(size_t)(b * NPIX + n0) * KSEL + i];
    __syncthreads();

    // corr[n_local][r]
    for (int e = tid; e < 64 * RCH; e += 256) {
        int nl = e >> 6, r = e & 63;
        const int* ip = &sidx[nl * KSEL];
        float s = 0.f;
#pragma unroll
        for (int j = 0; j < KSEL; j++)
            s += g_nf[((size_t)b * NPIX + ip[j]) * RCH + r];
        scorr[nl * SQS + r] = s * (1.f / 16.f);
    }
    __syncthreads();

    const int nl = tid & 63;
    const int cq = tid >> 6;
    float creg[RCH];
#pragma unroll
    for (int r4 = 0; r4 < RCH / 4; r4++) {
        float4 v = *reinterpret_cast<const float4*>(&scorr[nl * SQS + r4 * 4]);
        creg[r4 * 4 + 0] = v.x; creg[r4 * 4 + 1] = v.y;
        creg[r4 * 4 + 2] = v.z; creg[r4 * 4 + 3] = v.w;
    }

    const float* xrow = x   + (size_t)b * CH * NPIX + n0 + nl;
    float*       orow = out + (size_t)b * CH * NPIX + n0 + nl;
    for (int cc = 0; cc < 64; cc++) {
        const int c = cq * 64 + cc;
        float accv = 0.f;
        const float4* wrow = reinterpret_cast<const float4*>(&swp[c * RCH]);
#pragma unroll
        for (int r4 = 0; r4 < RCH / 4; r4++) {
            float4 wv = wrow[r4];            // broadcast LDS (all lanes same c)
            accv += wv.x * creg[r4 * 4 + 0] + wv.y * creg[r4 * 4 + 1]
                  + wv.z * creg[r4 * 4 + 2] + wv.w * creg[r4 * 4 + 3];
        }
        orow[(size_t)c * NPIX] = xrow[(size_t)c * NPIX] + accv;  // coalesced in nl
    }
}

// ---------------------------------------------------------------------------
extern "C" void kernel_launch(void* const* d_in, const int* in_sizes, int n_in,
                              void* d_out, int out_size)
{
    const float* x        = (const float*)d_in[0];
    const float* w_reduce = (const float*)d_in[1];
    const float* w_proj   = (const float*)d_in[2];
    float*       out      = (float*)d_out;

    const int smem1 = CH * SQS * 4;                                   // 69632
    const int smem2 = (TQ * SQS + RCH * SKS + TQ * SSS + TQ * KSEL) * 4
                    + TQ * KSEL * 4;                                  // 92416
    const int smem3 = CH * RCH * 4 + 64 * SQS * 4 + 64 * KSEL * 4;    // 87040

    cudaFuncSetAttribute(k1_reduce_norm, cudaFuncAttributeMaxDynamicSharedMemorySize, smem1);
    cudaFuncSetAttribute(k2_sim_topk,    cudaFuncAttributeMaxDynamicSharedMemorySize, smem2);
    cudaFuncSetAttribute(k3_gather_proj, cudaFuncAttributeMaxDynamicSharedMemorySize, smem3);

    k1_reduce_norm<<<(BATCH * NPIX) / 256, 256, smem1>>>(x, w_reduce);
    k2_sim_topk<<<dim3(NPIX / TQ, BATCH), 256, smem2>>>();
    k3_gather_proj<<<dim3(NPIX / 64, BATCH), 256, smem3>>>(x, w_proj, out);
}

// round 2
// speedup vs baseline: 1.0316x; 1.0316x over previous
#include <cuda_runtime.h>
#include <cstdint>

#define BATCH 2
#define CH    256
#define RCH   64
#define NPIX  9216
#define KSEL  16

// K2 tiling
#define TQ   128
#define TK   64
#define NKT  (NPIX / TK)     // 144
#define SQ2S 260             // sq2 row stride (floats), 1040B, 16B-aligned
#define SKS  68              // sk row stride
#define SSS  65              // sim row stride (odd -> conflict-free scan)

// scratch (device globals; no allocation allowed)
__device__ float g_nf [BATCH * NPIX * RCH];   // [b*N + n][r]
__device__ float g_nfT[BATCH * RCH * NPIX];   // [b][r][n]
__device__ int   g_topidx[BATCH * NPIX * KSEL];

union F2U { unsigned long long u; float2 f; };

// packed fp32x2 FMA (Blackwell FFMA2, 2x FFMA throughput)
#define FMA2(d, a, b) asm("fma.rn.f32x2 %0, %1, %2, %0;" : "+l"(d) : "l"(a), "l"(b))

// ---------------------------------------------------------------------------
// K1: feat = w_reduce @ x (per pixel), L2-normalize over rc, write nf & nfT.
// 288 CTAs x 256 threads; 64 pixels/CTA, 4 threads per pixel (16 channels each).
// ---------------------------------------------------------------------------
#define WSMS 68
__global__ __launch_bounds__(256) void k1_reduce_norm(
    const float* __restrict__ x, const float* __restrict__ w_reduce)
{
    extern __shared__ float sm[];
    float* wsm  = sm;                 // [c][r] stride 68
    float* sred = sm + CH * WSMS;     // [256]

    const int tid = threadIdx.x;
    const int pix = tid & 63;
    const int rg  = tid >> 6;         // 0..3 -> r chunk of 16

    for (int i = tid; i < RCH * CH; i += 256) {
        int r = i >> 8, c = i & 255;              // coalesced read w_reduce[r][c]
        wsm[c * WSMS + r] = w_reduce[i];
    }
    __syncthreads();

    const int p = blockIdx.x * 64 + pix;          // global pixel 0..18431
    const int b = p / NPIX;
    const int n = p % NPIX;

    unsigned long long f2[8];
#pragma unroll
    for (int j = 0; j < 8; j++) f2[j] = 0ull;

    const float* xp = x + (size_t)b * CH * NPIX + n;
    const float* wr = wsm + rg * 16;
#pragma unroll 4
    for (int c = 0; c < CH; c++) {
        float xv = xp[(size_t)c * NPIX];          // coalesced across pix
        unsigned long long xs;
        { F2U t; t.f.x = xv; t.f.y = xv; xs = t.u; }
        const ulonglong2* wrow = reinterpret_cast<const ulonglong2*>(wr + c * WSMS);
        ulonglong2 w0 = wrow[0];
        ulonglong2 w1 = wrow[1];
        ulonglong2 w2 = wrow[2];
        ulonglong2 w3 = wrow[3];
        FMA2(f2[0], xs, w0.x); FMA2(f2[1], xs, w0.y);
        FMA2(f2[2], xs, w1.x); FMA2(f2[3], xs, w1.y);
        FMA2(f2[4], xs, w2.x); FMA2(f2[5], xs, w2.y);
        FMA2(f2[6], xs, w3.x); FMA2(f2[7], xs, w3.y);
    }

    float feat[16];
#pragma unroll
    for (int j = 0; j < 8; j++) {
        F2U t; t.u = f2[j];
        feat[2 * j] = t.f.x; feat[2 * j + 1] = t.f.y;
    }
    float ssp = 0.f;
#pragma unroll
    for (int j = 0; j < 16; j++) ssp += feat[j] * feat[j];
    sred[tid] = ssp;
    __syncthreads();
    float ss = sred[pix] + sred[64 + pix] + sred[128 + pix] + sred[192 + pix];
    float inv = 1.f / fmaxf(sqrtf(ss), 1e-12f);

    float* nfp = g_nf + (size_t)p * RCH + rg * 16;
#pragma unroll
    for (int j4 = 0; j4 < 4; j4++) {
        float4 v;
        v.x = feat[j4 * 4 + 0] * inv;
        v.y = feat[j4 * 4 + 1] * inv;
        v.z = feat[j4 * 4 + 2] * inv;
        v.w = feat[j4 * 4 + 3] * inv;
        reinterpret_cast<float4*>(nfp)[j4] = v;
    }
    float* nft = g_nfT + (size_t)b * RCH * NPIX + (size_t)(rg * 16) * NPIX + n;
#pragma unroll
    for (int j = 0; j < 16; j++)
        nft[(size_t)j * NPIX] = feat[j] * inv;    // coalesced across pix
}

// ---------------------------------------------------------------------------
// K2: fused sim-GEMM (FFMA2, pre-splatted A) + streaming top-16 per query row.
// 512 threads; CTA = 128 q-rows; loops 144 key tiles of 64.
// Thread tile 4q x 4k. Double-buffered key tile; scan overlapped with load.
// ---------------------------------------------------------------------------
__global__ __launch_bounds__(512, 1) void k2_sim_topk()
{
    extern __shared__ float sm[];
    float* sq2  = sm;                           // [64][SQ2S] A duplicated pairs
    float* sk   = sq2 + RCH * SQ2S;             // [2][64][SKS]
    float* ssim = sk + 2 * RCH * SKS;           // [128][SSS]
    float* tval = ssim + TQ * SSS;              // [128][16]
    int*   tidx = reinterpret_cast<int*>(tval + TQ * KSEL);

    const int tid = threadIdx.x;
    const int b   = blockIdx.y;
    const int q0  = blockIdx.x * TQ;
    const int tx  = tid & 15;                   // k group (4 cols)
    const int ty  = tid >> 4;                   // q group (4 rows), 0..31

    // load + duplicate query tile: sq2[r][2q]=sq2[r][2q+1]=nfT[r][q0+q]
    for (int i = tid; i < RCH * TQ; i += 512) {
        int r = i >> 7, q = i & 127;
        float v = g_nfT[((size_t)b * RCH + r) * NPIX + q0 + q];
        sq2[r * SQ2S + 2 * q]     = v;
        sq2[r * SQ2S + 2 * q + 1] = v;
    }
    // prologue: key tile 0
    for (int i = tid; i < RCH * TK; i += 512) {
        int r = i >> 6, k = i & 63;
        sk[r * SKS + k] = g_nfT[((size_t)b * RCH + r) * NPIX + k];
    }
    if (tid < TQ) {
#pragma unroll
        for (int j = 0; j < KSEL; j++) { tval[tid * KSEL + j] = -3.4e38f; tidx[tid * KSEL + j] = 0; }
    }
    __syncthreads();

    for (int kt = 0; kt < NKT; kt++) {
        const float* skc = sk + (kt & 1) * (RCH * SKS);

        unsigned long long acc[4][2];
#pragma unroll
        for (int i = 0; i < 4; i++) { acc[i][0] = 0ull; acc[i][1] = 0ull; }

        const float* sqb = sq2 + ty * 8;
        const float* skb = skc + tx * 4;
#pragma unroll 8
        for (int r = 0; r < RCH; r++) {
            ulonglong2 a01 = *reinterpret_cast<const ulonglong2*>(sqb + r * SQ2S);
            ulonglong2 a23 = *reinterpret_cast<const ulonglong2*>(sqb + r * SQ2S + 4);
            ulonglong2 bv  = *reinterpret_cast<const ulonglong2*>(skb + r * SKS);
            FMA2(acc[0][0], a01.x, bv.x); FMA2(acc[0][1], a01.x, bv.y);
            FMA2(acc[1][0], a01.y, bv.x); FMA2(acc[1][1], a01.y, bv.y);
            FMA2(acc[2][0], a23.x, bv.x); FMA2(acc[2][1], a23.x, bv.y);
            FMA2(acc[3][0], a23.y, bv.x); FMA2(acc[3][1], a23.y, bv.y);
        }

        // dump sim tile
#pragma unroll
        for (int i = 0; i < 4; i++) {
            float* sr = &ssim[(ty * 4 + i) * SSS + tx * 4];
            F2U t0; t0.u = acc[i][0];
            F2U t1; t1.u = acc[i][1];
            sr[0] = t0.f.x; sr[1] = t0.f.y;
            sr[2] = t1.f.x; sr[3] = t1.f.y;
        }
        __syncthreads();

        if (tid < TQ) {
            // owner scan: threshold-gated stable insertion into sorted top-16
            float* tv = &tval[tid * KSEL];
            int*   ti = &tidx[tid * KSEL];
            float  thr = tv[KSEL - 1];
            const float* srow = &ssim[tid * SSS];
            const int k0 = kt * TK;
            for (int p = 0; p < TK; p++) {
                float v = srow[p];
                if (v > thr) {
                    int j = KSEL - 1;
                    while (j > 0 && tv[j - 1] < v) {   // strict: lower index wins ties
                        tv[j] = tv[j - 1]; ti[j] = ti[j - 1]; j--;
                    }
                    tv[j] = v; ti[j] = k0 + p;
                    thr = tv[KSEL - 1];
                }
            }
        } else if (kt + 1 < NKT) {
            // other 384 threads: load next key tile
            float* skn = sk + ((kt + 1) & 1) * (RCH * SKS);
            const size_t base = (size_t)b * RCH * NPIX + (size_t)(kt + 1) * TK;
            for (int i = tid - TQ; i < RCH * TK; i += 512 - TQ) {
                int r = i >> 6, k = i & 63;
                skn[r * SKS + k] = g_nfT[base + (size_t)r * NPIX + k];
            }
        }
        __syncthreads();
    }

    if (tid < TQ) {
        int* dst = &g_topidx[(size_t)(b * NPIX + q0 + tid) * KSEL];
#pragma unroll
        for (int j = 0; j < KSEL; j++) dst[j] = tidx[tid * KSEL + j];
    }
}

// ---------------------------------------------------------------------------
// K3: corr = mean of 16 gathered nf rows; out = x + w_proj @ corr
// ---------------------------------------------------------------------------
#define SQS 68
__global__ __launch_bounds__(256) void k3_gather_proj(
    const float* __restrict__ x, const float* __restrict__ w_proj,
    float* __restrict__ out)
{
    extern __shared__ float sm[];
    float* swp   = sm;                       // [256][64] w_proj
    float* scorr = swp + CH * RCH;           // [64][SQS]
    int*   sidx  = reinterpret_cast<int*>(scorr + 64 * SQS);  // [64][16]

    const int tid = threadIdx.x;
    const int b   = blockIdx.y;
    const int n0  = blockIdx.x * 64;

    for (int i = tid; i < CH * RCH; i += 256) swp[i] = w_proj[i];
    for (int i = tid; i < 64 * KSEL; i += 256)
        sidx[i] = g_topidx[(size_t)(b * NPIX + n0) * KSEL + i];
    __syncthreads();

    for (int e = tid; e < 64 * RCH; e += 256) {
        int nl = e >> 6, r = e & 63;
        const int* ip = &sidx[nl * KSEL];
        float s = 0.f;
#pragma unroll
        for (int j = 0; j < KSEL; j++)
            s += g_nf[((size_t)b * NPIX + ip[j]) * RCH + r];
        scorr[nl * SQS + r] = s * (1.f / 16.f);
    }
    __syncthreads();

    const int nl = tid & 63;
    const int cq = tid >> 6;
    float creg[RCH];
#pragma unroll
    for (int r4 = 0; r4 < RCH / 4; r4++) {
        float4 v = *reinterpret_cast<const float4*>(&scorr[nl * SQS + r4 * 4]);
        creg[r4 * 4 + 0] = v.x; creg[r4 * 4 + 1] = v.y;
        creg[r4 * 4 + 2] = v.z; creg[r4 * 4 + 3] = v.w;
    }

    const float* xrow = x   + (size_t)b * CH * NPIX + n0 + nl;
    float*       orow = out + (size_t)b * CH * NPIX + n0 + nl;
    for (int cc = 0; cc < 64; cc++) {
        const int c = cq * 64 + cc;
        float accv = 0.f;
        const float4* wrow = reinterpret_cast<const float4*>(&swp[c * RCH]);
#pragma unroll
        for (int r4 = 0; r4 < RCH / 4; r4++) {
            float4 wv = wrow[r4];
            accv += wv.x * creg[r4 * 4 + 0] + wv.y * creg[r4 * 4 + 1]
                  + wv.z * creg[r4 * 4 + 2] + wv.w * creg[r4 * 4 + 3];
        }
        orow[(size_t)c * NPIX] = xrow[(size_t)c * NPIX] + accv;
    }
}

// ---------------------------------------------------------------------------
extern "C" void kernel_launch(void* const* d_in, const int* in_sizes, int n_in,
                              void* d_out, int out_size)
{
    const float* x        = (const float*)d_in[0];
    const float* w_reduce = (const float*)d_in[1];
    const float* w_proj   = (const float*)d_in[2];
    float*       out      = (float*)d_out;

    const int smem1 = (CH * WSMS + 256) * 4;                              // ~70.7KB
    const int smem2 = (RCH * SQ2S + 2 * RCH * SKS + TQ * SSS) * 4
                    + TQ * KSEL * 8;                                      // 151,040B
    const int smem3 = CH * RCH * 4 + 64 * SQS * 4 + 64 * KSEL * 4;        // 87,040B

    cudaFuncSetAttribute(k1_reduce_norm, cudaFuncAttributeMaxDynamicSharedMemorySize, smem1);
    cudaFuncSetAttribute(k2_sim_topk,    cudaFuncAttributeMaxDynamicSharedMemorySize, smem2);
    cudaFuncSetAttribute(k3_gather_proj, cudaFuncAttributeMaxDynamicSharedMemorySize, smem3);

    k1_reduce_norm<<<(BATCH * NPIX) / 64, 256, smem1>>>(x, w_reduce);
    k2_sim_topk<<<dim3(NPIX / TQ, BATCH), 512, smem2>>>();
    k3_gather_proj<<<dim3(NPIX / 64, BATCH), 256, smem3>>>(x, w_proj, out);
}

// round 3
// speedup vs baseline: 1.5591x; 1.5113x over previous
#include <cuda_runtime.h>
#include <cstdint>
#include <cfloat>

#define BATCH 2
#define CH    256
#define RCH   64
#define NPIX  9216
#define KSEL  16

// K2 tiling
#define TQ   128
#define TK   128
#define NKT  (NPIX / TK)     // 72
#define SQ2S 260             // splatted q row stride (floats)
#define SKS  132             // key tile row stride
#define SSS  132             // sim row stride: lanes 0-7 scan rows 8w+i -> banks i*4, conflict-free

// scratch (device globals; no allocation allowed)
__device__ float g_nf [BATCH * NPIX * RCH];   // [b*N + n][r]
__device__ float g_nfT[BATCH * RCH * NPIX];   // [b][r][n]
__device__ int   g_topidx[BATCH * NPIX * KSEL];

union F2U { unsigned long long u; float2 f; };

// packed fp32x2 FMA
#define FMA2(d, a, b) asm("fma.rn.f32x2 %0, %1, %2, %0;" : "+l"(d) : "l"(a), "l"(b))

// ---------------------------------------------------------------------------
// K1: feat = w_reduce @ x (per pixel), L2-normalize over rc, write nf & nfT.
// ---------------------------------------------------------------------------
#define WSMS 68
__global__ __launch_bounds__(256) void k1_reduce_norm(
    const float* __restrict__ x, const float* __restrict__ w_reduce)
{
    extern __shared__ float sm[];
    float* wsm  = sm;                 // [c][r] stride 68
    float* sred = sm + CH * WSMS;     // [256]

    const int tid = threadIdx.x;
    const int pix = tid & 63;
    const int rg  = tid >> 6;         // 0..3 -> r chunk of 16

    for (int i = tid; i < RCH * CH; i += 256) {
        int r = i >> 8, c = i & 255;
        wsm[c * WSMS + r] = w_reduce[i];
    }
    __syncthreads();

    const int p = blockIdx.x * 64 + pix;
    const int b = p / NPIX;
    const int n = p % NPIX;

    unsigned long long f2[8];
#pragma unroll
    for (int j = 0; j < 8; j++) f2[j] = 0ull;

    const float* xp = x + (size_t)b * CH * NPIX + n;
    const float* wr = wsm + rg * 16;
#pragma unroll 4
    for (int c = 0; c < CH; c++) {
        float xv = xp[(size_t)c * NPIX];
        unsigned long long xs;
        { F2U t; t.f.x = xv; t.f.y = xv; xs = t.u; }
        const ulonglong2* wrow = reinterpret_cast<const ulonglong2*>(wr + c * WSMS);
        ulonglong2 w0 = wrow[0];
        ulonglong2 w1 = wrow[1];
        ulonglong2 w2 = wrow[2];
        ulonglong2 w3 = wrow[3];
        FMA2(f2[0], xs, w0.x); FMA2(f2[1], xs, w0.y);
        FMA2(f2[2], xs, w1.x); FMA2(f2[3], xs, w1.y);
        FMA2(f2[4], xs, w2.x); FMA2(f2[5], xs, w2.y);
        FMA2(f2[6], xs, w3.x); FMA2(f2[7], xs, w3.y);
    }

    float feat[16];
#pragma unroll
    for (int j = 0; j < 8; j++) {
        F2U t; t.u = f2[j];
        feat[2 * j] = t.f.x; feat[2 * j + 1] = t.f.y;
    }
    float ssp = 0.f;
#pragma unroll
    for (int j = 0; j < 16; j++) ssp += feat[j] * feat[j];
    sred[tid] = ssp;
    __syncthreads();
    float ss = sred[pix] + sred[64 + pix] + sred[128 + pix] + sred[192 + pix];
    float inv = 1.f / fmaxf(sqrtf(ss), 1e-12f);

    float* nfp = g_nf + (size_t)p * RCH + rg * 16;
#pragma unroll
    for (int j4 = 0; j4 < 4; j4++) {
        float4 v;
        v.x = feat[j4 * 4 + 0] * inv;
        v.y = feat[j4 * 4 + 1] * inv;
        v.z = feat[j4 * 4 + 2] * inv;
        v.w = feat[j4 * 4 + 3] * inv;
        reinterpret_cast<float4*>(nfp)[j4] = v;
    }
    float* nft = g_nfT + (size_t)b * RCH * NPIX + (size_t)(rg * 16) * NPIX + n;
#pragma unroll
    for (int j = 0; j < 16; j++)
        nft[(size_t)j * NPIX] = feat[j] * inv;
}

// ---------------------------------------------------------------------------
// K2: fused 128x128 sim tiles (FFMA2) + register-gated streaming top-16.
// 512 threads; thread tile 4q x 8k (cols {4tx..4tx+3} and {64+4tx..64+4tx+3}).
// Epilogue: per-row reg max vs lagged threshold; only flagged segments are
// dumped + flagged. Scan phase: lanes 0-7/warp own 8 consecutive rows and
// process flagged segments in ascending col order; lanes 8-31 load next tile.
// ---------------------------------------------------------------------------
__global__ __launch_bounds__(512, 1) void k2_sim_topk()
{
    extern __shared__ float sm[];
    float* sq2   = sm;                          // [64][SQ2S] splatted q pairs
    float* sk    = sq2 + RCH * SQ2S;            // [64][SKS]
    float* ssim  = sk + RCH * SKS;              // [128][SSS]
    float* tval  = ssim + TQ * SSS;             // [128][16]
    int*   tidx  = reinterpret_cast<int*>(tval + TQ * KSEL);       // [128][16]
    float* thr   = reinterpret_cast<float*>(tidx + TQ * KSEL);     // [128]
    unsigned char* flags = reinterpret_cast<unsigned char*>(thr + TQ); // [128][16]

    const int tid = threadIdx.x;
    const int b   = blockIdx.y;
    const int q0  = blockIdx.x * TQ;
    const int tx  = tid & 15;     // col group
    const int ty  = tid >> 4;     // row group 0..31 (rows 4ty..4ty+3)
    const int w   = tid >> 5;     // warp 0..15
    const int l   = tid & 31;

    // load + splat query tile
    for (int i = tid; i < RCH * TQ; i += 512) {
        int r = i >> 7, q = i & 127;
        float v = g_nfT[((size_t)b * RCH + r) * NPIX + q0 + q];
        sq2[r * SQ2S + 2 * q]     = v;
        sq2[r * SQ2S + 2 * q + 1] = v;
    }
    // key tile 0
    for (int i = tid; i < RCH * TK; i += 512) {
        int r = i >> 7, k = i & 127;
        sk[r * SKS + k] = g_nfT[((size_t)b * RCH + r) * NPIX + k];
    }
    if (tid < TQ) {
#pragma unroll
        for (int j = 0; j < KSEL; j++) { tval[tid * KSEL + j] = -FLT_MAX; tidx[tid * KSEL + j] = 0; }
        thr[tid] = -FLT_MAX;
    }
    for (int i = tid; i < (TQ * 16) / 4; i += 512)
        reinterpret_cast<uint32_t*>(flags)[i] = 0u;
    __syncthreads();

    for (int kt = 0; kt < NKT; kt++) {
        // ---- GEMM ----
        unsigned long long acc[4][4];
#pragma unroll
        for (int i = 0; i < 4; i++)
#pragma unroll
            for (int j = 0; j < 4; j++) acc[i][j] = 0ull;

        const float* sqb = sq2 + ty * 8;
        const float* skb = sk + tx * 4;
#pragma unroll 8
        for (int r = 0; r < RCH; r++) {
            ulonglong2 a01 = *reinterpret_cast<const ulonglong2*>(sqb + r * SQ2S);
            ulonglong2 a23 = *reinterpret_cast<const ulonglong2*>(sqb + r * SQ2S + 4);
            ulonglong2 b0  = *reinterpret_cast<const ulonglong2*>(skb + r * SKS);
            ulonglong2 b1  = *reinterpret_cast<const ulonglong2*>(skb + r * SKS + 64);
            FMA2(acc[0][0], a01.x, b0.x); FMA2(acc[0][1], a01.x, b0.y);
            FMA2(acc[0][2], a01.x, b1.x); FMA2(acc[0][3], a01.x, b1.y);
            FMA2(acc[1][0], a01.y, b0.x); FMA2(acc[1][1], a01.y, b0.y);
            FMA2(acc[1][2], a01.y, b1.x); FMA2(acc[1][3], a01.y, b1.y);
            FMA2(acc[2][0], a23.x, b0.x); FMA2(acc[2][1], a23.x, b0.y);
            FMA2(acc[2][2], a23.x, b1.x); FMA2(acc[2][3], a23.x, b1.y);
            FMA2(acc[3][0], a23.y, b0.x); FMA2(acc[3][1], a23.y, b0.y);
            FMA2(acc[3][2], a23.y, b1.x); FMA2(acc[3][3], a23.y, b1.y);
        }

        // ---- epilogue: register-gated dump ----
#pragma unroll
        for (int i = 0; i < 4; i++) {
            F2U u0, u1, u2, u3;
            u0.u = acc[i][0]; u1.u = acc[i][1]; u2.u = acc[i][2]; u3.u = acc[i][3];
            float m = fmaxf(fmaxf(fmaxf(u0.f.x, u0.f.y), fmaxf(u1.f.x, u1.f.y)),
                            fmaxf(fmaxf(u2.f.x, u2.f.y), fmaxf(u3.f.x, u3.f.y)));
            const int row = 4 * ty + i;
            if (m > thr[row]) {
                flags[row * 16 + tx] = 1;
                float4 v0; v0.x = u0.f.x; v0.y = u0.f.y; v0.z = u1.f.x; v0.w = u1.f.y;
                float4 v1; v1.x = u2.f.x; v1.y = u2.f.y; v1.z = u3.f.x; v1.w = u3.f.y;
                *reinterpret_cast<float4*>(&ssim[row * SSS + 4 * tx])      = v0;
                *reinterpret_cast<float4*>(&ssim[row * SSS + 64 + 4 * tx]) = v1;
            }
        }
        __syncthreads();   // A: dumps + flags visible; GEMM done reading sk

        // ---- scan (lanes 0-7) + next-tile load (lanes 8-31) ----
        if (l < 8) {
            const int row = w * 8 + l;
            uint4 fb = *reinterpret_cast<const uint4*>(&flags[row * 16]);
            if (fb.x | fb.y | fb.z | fb.w) {
                float* tv = &tval[row * KSEL];
                int*   ti = &tidx[row * KSEL];
                const unsigned char* fbb = &flags[row * 16];
                const float* srow = &ssim[row * SSS];
                const int kbase = kt * TK;
#pragma unroll 1
                for (int half = 0; half < 2; half++) {
                    const int cbase = half * 64;
                    for (int t = 0; t < 16; t++) {
                        if (!fbb[t]) continue;
                        float4 v = *reinterpret_cast<const float4*>(&srow[cbase + 4 * t]);
                        float vv[4] = {v.x, v.y, v.z, v.w};
#pragma unroll
                        for (int u = 0; u < 4; u++) {
                            float val = vv[u];
                            if (val > tv[KSEL - 1]) {
                                int j = KSEL - 1;
                                while (j > 0 && tv[j - 1] < val) {  // strict: lower index wins ties
                                    tv[j] = tv[j - 1]; ti[j] = ti[j - 1]; j--;
                                }
                                tv[j] = val; ti[j] = kbase + cbase + 4 * t + u;
                            }
                        }
                    }
                }
                thr[row] = tv[KSEL - 1];
                *reinterpret_cast<uint4*>(&flags[row * 16]) = make_uint4(0, 0, 0, 0);
            }
        } else if (kt + 1 < NKT) {
            const int lidx = w * 24 + (l - 8);     // 0..383
            const size_t base = (size_t)b * RCH * NPIX + (size_t)(kt + 1) * TK;
            for (int e = lidx; e < RCH * TK; e += 384) {
                int r = e >> 7, k = e & 127;
                sk[r * SKS + k] = g_nfT[base + (size_t)r * NPIX + k];
            }
        }
        __syncthreads();   // B: sk(t+1), thresholds, cleared flags visible
    }

    if (l < 8) {
        const int row = w * 8 + l;
        int* dst = &g_topidx[(size_t)(b * NPIX + q0 + row) * KSEL];
#pragma unroll
        for (int j = 0; j < KSEL; j++) dst[j] = tidx[row * KSEL + j];
    }
}

// ---------------------------------------------------------------------------
// K3: corr = mean of 16 gathered nf rows; out = x + w_proj @ corr
// ---------------------------------------------------------------------------
#define SQS 68
__global__ __launch_bounds__(256) void k3_gather_proj(
    const float* __restrict__ x, const float* __restrict__ w_proj,
    float* __restrict__ out)
{
    extern __shared__ float sm[];
    float* swp   = sm;                       // [256][64] w_proj
    float* scorr = swp + CH * RCH;           // [64][SQS]
    int*   sidx  = reinterpret_cast<int*>(scorr + 64 * SQS);  // [64][16]

    const int tid = threadIdx.x;
    const int b   = blockIdx.y;
    const int n0  = blockIdx.x * 64;

    for (int i = tid; i < CH * RCH; i += 256) swp[i] = w_proj[i];
    for (int i = tid; i < 64 * KSEL; i += 256)
        sidx[i] = g_topidx[(size_t)(b * NPIX + n0) * KSEL + i];
    __syncthreads();

    for (int e = tid; e < 64 * RCH; e += 256) {
        int nl = e >> 6, r = e & 63;
        const int* ip = &sidx[nl * KSEL];
        float s = 0.f;
#pragma unroll
        for (int j = 0; j < KSEL; j++)
            s += g_nf[((size_t)b * NPIX + ip[j]) * RCH + r];
        scorr[nl * SQS + r] = s * (1.f / 16.f);
    }
    __syncthreads();

    const int nl = tid & 63;
    const int cq = tid >> 6;
    float creg[RCH];
#pragma unroll
    for (int r4 = 0; r4 < RCH / 4; r4++) {
        float4 v = *reinterpret_cast<const float4*>(&scorr[nl * SQS + r4 * 4]);
        creg[r4 * 4 + 0] = v.x; creg[r4 * 4 + 1] = v.y;
        creg[r4 * 4 + 2] = v.z; creg[r4 * 4 + 3] = v.w;
    }

    const float* xrow = x   + (size_t)b * CH * NPIX + n0 + nl;
    float*       orow = out + (size_t)b * CH * NPIX + n0 + nl;
    for (int cc = 0; cc < 64; cc++) {
        const int c = cq * 64 + cc;
        float accv = 0.f;
        const float4* wrow = reinterpret_cast<const float4*>(&swp[c * RCH]);
#pragma unroll
        for (int r4 = 0; r4 < RCH / 4; r4++) {
            float4 wv = wrow[r4];
            accv += wv.x * creg[r4 * 4 + 0] + wv.y * creg[r4 * 4 + 1]
                  + wv.z * creg[r4 * 4 + 2] + wv.w * creg[r4 * 4 + 3];
        }
        orow[(size_t)c * NPIX] = xrow[(size_t)c * NPIX] + accv;
    }
}

// ---------------------------------------------------------------------------
extern "C" void kernel_launch(void* const* d_in, const int* in_sizes, int n_in,
                              void* d_out, int out_size)
{
    const float* x        = (const float*)d_in[0];
    const float* w_reduce = (const float*)d_in[1];
    const float* w_proj   = (const float*)d_in[2];
    float*       out      = (float*)d_out;

    const int smem1 = (CH * WSMS + 256) * 4;
    const int smem2 = (RCH * SQ2S + RCH * SKS + TQ * SSS) * 4   // tiles
                    + TQ * KSEL * 8                              // tval+tidx
                    + TQ * 4                                     // thr
                    + TQ * 16;                                   // flags
    const int smem3 = CH * RCH * 4 + 64 * SQS * 4 + 64 * KSEL * 4;

    cudaFuncSetAttribute(k1_reduce_norm, cudaFuncAttributeMaxDynamicSharedMemorySize, smem1);
    cudaFuncSetAttribute(k2_sim_topk,    cudaFuncAttributeMaxDynamicSharedMemorySize, smem2);
    cudaFuncSetAttribute(k3_gather_proj, cudaFuncAttributeMaxDynamicSharedMemorySize, smem3);

    k1_reduce_norm<<<(BATCH * NPIX) / 64, 256, smem1>>>(x, w_reduce);
    k2_sim_topk<<<dim3(NPIX / TQ, BATCH), 512, smem2>>>();
    k3_gather_proj<<<dim3(NPIX / 64, BATCH), 256, smem3>>>(x, w_proj, out);
}

// round 5
// speedup vs baseline: 1.7407x; 1.1164x over previous
#include <cuda_runtime.h>
#include <cuda_fp16.h>
#include <cstdint>
#include <cfloat>

#define BATCH 2
#define CH    256
#define RCH   64
#define NPIX  9216
#define KSEL  16

// K2 tiling
#define TM   128
#define TN   128
#define NKT  (NPIX / TN)      // 72
#define ARS  144              // fp16 tile row stride in BYTES (64*2 + 16 pad)
#define PLANE (128 * ARS)     // 18432 B

// scratch (device globals; no allocation allowed)
__device__ float  g_nf[BATCH * NPIX * RCH];          // fp32 normalized feats (K3)
__device__ __half g_hs[2][BATCH * NPIX * RCH];       // fp16 split planes [p][(b*N+n)*64+r]
__device__ int    g_topidx[BATCH * NPIX * KSEL];

union F2U { unsigned long long u; float2 f; };
#define FMA2(d, a, b) asm("fma.rn.f32x2 %0, %1, %2, %0;" : "+l"(d) : "l"(a), "l"(b))

__device__ __forceinline__ uint32_t smem_u32(const void* p) {
    uint32_t a;
    asm("{ .reg .u64 t; cvta.to.shared.u64 t, %1; cvt.u32.u64 %0, t; }" : "=r"(a) : "l"(p));
    return a;
}
#define LDSM_X4(r0, r1, r2, r3, addr) \
    asm volatile("ldmatrix.sync.aligned.m8n8.x4.shared.b16 {%0,%1,%2,%3}, [%4];" \
                 : "=r"(r0), "=r"(r1), "=r"(r2), "=r"(r3) : "r"(addr))
#define LDSM_X2(r0, r1, addr) \
    asm volatile("ldmatrix.sync.aligned.m8n8.x2.shared.b16 {%0,%1}, [%2];" \
                 : "=r"(r0), "=r"(r1) : "r"(addr))
#define MMA16816(c0, c1, c2, c3, a0, a1, a2, a3, b0, b1) \
    asm volatile("mma.sync.aligned.m16n8k16.row.col.f32.f16.f16.f32 " \
                 "{%0,%1,%2,%3}, {%4,%5,%6,%7}, {%8,%9}, {%0,%1,%2,%3};" \
                 : "+f"(c0), "+f"(c1), "+f"(c2), "+f"(c3) \
                 : "r"(a0), "r"(a1), "r"(a2), "r"(a3), "r"(b0), "r"(b1))

// ---------------------------------------------------------------------------
// K1: feat = w_reduce @ x, L2-normalize; write g_nf + fp16 split planes.
// ---------------------------------------------------------------------------
#define WSMS 68
__global__ __launch_bounds__(256) void k1_reduce_norm(
    const float* __restrict__ x, const float* __restrict__ w_reduce)
{
    extern __shared__ float sm[];
    float* wsm  = sm;
    float* sred = sm + CH * WSMS;

    const int tid = threadIdx.x;
    const int pix = tid & 63;
    const int rg  = tid >> 6;

    for (int i = tid; i < RCH * CH; i += 256) {
        int r = i >> 8, c = i & 255;
        wsm[c * WSMS + r] = w_reduce[i];
    }
    __syncthreads();

    const int p = blockIdx.x * 64 + pix;
    const int b = p / NPIX;
    const int n = p % NPIX;

    unsigned long long f2[8];
#pragma unroll
    for (int j = 0; j < 8; j++) f2[j] = 0ull;

    const float* xp = x + (size_t)b * CH * NPIX + n;
    const float* wr = wsm + rg * 16;
#pragma unroll 4
    for (int c = 0; c < CH; c++) {
        float xv = xp[(size_t)c * NPIX];
        unsigned long long xs;
        { F2U t; t.f.x = xv; t.f.y = xv; xs = t.u; }
        const ulonglong2* wrow = reinterpret_cast<const ulonglong2*>(wr + c * WSMS);
        ulonglong2 w0 = wrow[0], w1 = wrow[1], w2 = wrow[2], w3 = wrow[3];
        FMA2(f2[0], xs, w0.x); FMA2(f2[1], xs, w0.y);
        FMA2(f2[2], xs, w1.x); FMA2(f2[3], xs, w1.y);
        FMA2(f2[4], xs, w2.x); FMA2(f2[5], xs, w2.y);
        FMA2(f2[6], xs, w3.x); FMA2(f2[7], xs, w3.y);
    }

    float feat[16];
#pragma unroll
    for (int j = 0; j < 8; j++) { F2U t; t.u = f2[j]; feat[2*j] = t.f.x; feat[2*j+1] = t.f.y; }
    float ssp = 0.f;
#pragma unroll
    for (int j = 0; j < 16; j++) ssp += feat[j] * feat[j];
    sred[tid] = ssp;
    __syncthreads();
    float ss = sred[pix] + sred[64 + pix] + sred[128 + pix] + sred[192 + pix];
    float inv = 1.f / fmaxf(sqrtf(ss), 1e-12f);

    float* nfp = g_nf + (size_t)p * RCH + rg * 16;
#pragma unroll
    for (int j4 = 0; j4 < 4; j4++) {
        float4 v;
        v.x = feat[j4*4+0] * inv; v.y = feat[j4*4+1] * inv;
        v.z = feat[j4*4+2] * inv; v.w = feat[j4*4+3] * inv;
        reinterpret_cast<float4*>(nfp)[j4] = v;
    }

    // fp16 2-way split (Markidis): v = h0 + h1 (+ ~2^-24)
    uint32_t p0[8], p1[8];
#pragma unroll
    for (int j = 0; j < 8; j++) {
        float va = feat[2*j]   * inv;
        float vb = feat[2*j+1] * inv;
        __half a0 = __float2half_rn(va);
        __half b0 = __float2half_rn(vb);
        __half a1 = __float2half_rn(va - __half2float(a0));
        __half b1 = __float2half_rn(vb - __half2float(b0));
        p0[j] = (uint32_t)__half_as_ushort(a0) | ((uint32_t)__half_as_ushort(b0) << 16);
        p1[j] = (uint32_t)__half_as_ushort(a1) | ((uint32_t)__half_as_ushort(b1) << 16);
    }
    size_t eoff = (size_t)p * RCH + rg * 16;
    uint4* d0 = reinterpret_cast<uint4*>(&g_hs[0][eoff]);
    uint4* d1 = reinterpret_cast<uint4*>(&g_hs[1][eoff]);
    d0[0] = make_uint4(p0[0], p0[1], p0[2], p0[3]);
    d0[1] = make_uint4(p0[4], p0[5], p0[6], p0[7]);
    d1[0] = make_uint4(p1[0], p1[1], p1[2], p1[3]);
    d1[1] = make_uint4(p1[4], p1[5], p1[6], p1[7]);
}

// ---------------------------------------------------------------------------
// K2: HMMA fp16-split sim GEMM + register-gated streaming top-16.
// 256 threads (8 warps, 2x4 warp grid; warp tile 64m x 32n).
// ---------------------------------------------------------------------------
#define A_OFF    0                         // 2 planes
#define B_OFF    (2 * PLANE)               // 2 bufs x 2 planes
#define SSIM_OFF (B_OFF + 4 * PLANE)       // [128][132] f32
#define TVAL_OFF (SSIM_OFF + 128 * 132 * 4)
#define TIDX_OFF (TVAL_OFF + 128 * KSEL * 4)
#define THR_OFF  (TIDX_OFF + 128 * KSEL * 4)
#define FLAG_OFF (THR_OFF + 128 * 4)       // uchar[128][4] (read as uint per row)
#define SMEM_K2  (FLAG_OFF + 128 * 4)

__global__ __launch_bounds__(256, 1) void k2_sim_topk()
{
    extern __shared__ char smc[];
    const uint32_t sb = smem_u32(smc);
    float* ssim = reinterpret_cast<float*>(smc + SSIM_OFF);
    float* tval = reinterpret_cast<float*>(smc + TVAL_OFF);
    int*   tidx = reinterpret_cast<int*>(smc + TIDX_OFF);
    float* thr  = reinterpret_cast<float*>(smc + THR_OFF);
    unsigned char* flags = reinterpret_cast<unsigned char*>(smc + FLAG_OFF);
    uint32_t* flagw = reinterpret_cast<uint32_t*>(smc + FLAG_OFF);

    const int tid = threadIdx.x;
    const int wid = tid >> 5;
    const int l   = tid & 31;
    const int g   = l >> 2;          // mma group row
    const int tg  = l & 3;           // thread in group
    const int wm  = wid >> 2;        // 0..1
    const int wn  = wid & 3;         // 0..3
    const int b   = blockIdx.y;
    const int q0  = blockIdx.x * TM;

    // ---- prologue: A planes (persistent) + B tile 0 into buf 0 ----
    {
        const size_t qrow = (size_t)(b * NPIX + q0) * RCH;
#pragma unroll
        for (int pl = 0; pl < 2; pl++) {
            const uint4* src = reinterpret_cast<const uint4*>(&g_hs[pl][qrow]);
            char* dst = smc + A_OFF + pl * PLANE;
            for (int e = tid; e < 1024; e += 256) {   // 128 rows x 8 chunks
                int i = e >> 3, j = e & 7;
                *reinterpret_cast<uint4*>(dst + i * ARS + j * 16) = src[e];
            }
        }
        const size_t krow = (size_t)(b * NPIX) * RCH;
#pragma unroll
        for (int pl = 0; pl < 2; pl++) {
            const uint4* src = reinterpret_cast<const uint4*>(&g_hs[pl][krow]);
            char* dst = smc + B_OFF + pl * PLANE;
            for (int e = tid; e < 1024; e += 256) {
                int i = e >> 3, j = e & 7;
                *reinterpret_cast<uint4*>(dst + i * ARS + j * 16) = src[e];
            }
        }
    }
    if (tid < TM) {
#pragma unroll
        for (int j = 0; j < KSEL; j++) { tval[tid * KSEL + j] = -FLT_MAX; tidx[tid * KSEL + j] = 0; }
        thr[tid] = -FLT_MAX;
        flagw[tid] = 0u;
    }
    __syncthreads();

    // per-thread ldmatrix lane offsets
    const uint32_t a_lane = (uint32_t)((l & 15) * ARS + (l >> 4) * 16);
    const uint32_t b_lane = (uint32_t)((l & 7) * ARS + ((l >> 3) & 1) * 16);
    const uint32_t aP0 = sb + A_OFF + (uint32_t)(wm * 64) * ARS + a_lane;
    const uint32_t aP1 = aP0 + PLANE;

    for (int kt = 0; kt < NKT; kt++) {
        const uint32_t bBase = sb + B_OFF + (uint32_t)((kt & 1) * 2) * PLANE
                             + (uint32_t)(wn * 32) * ARS + b_lane;

        float c[4][4][4];
#pragma unroll
        for (int mf = 0; mf < 4; mf++)
#pragma unroll
            for (int nf = 0; nf < 4; nf++) { c[mf][nf][0]=0.f; c[mf][nf][1]=0.f; c[mf][nf][2]=0.f; c[mf][nf][3]=0.f; }

#pragma unroll
        for (int kk = 0; kk < 4; kk++) {
            const uint32_t koff = (uint32_t)(kk * 32);
            uint32_t a[4][4], b0[4][2], b1[4][2];
#pragma unroll
            for (int mf = 0; mf < 4; mf++)
                LDSM_X4(a[mf][0], a[mf][1], a[mf][2], a[mf][3],
                        aP0 + (uint32_t)(mf * 16) * ARS + koff);
#pragma unroll
            for (int nf = 0; nf < 4; nf++)
                LDSM_X2(b0[nf][0], b0[nf][1], bBase + (uint32_t)(nf * 8) * ARS + koff);
#pragma unroll
            for (int nf = 0; nf < 4; nf++)
                LDSM_X2(b1[nf][0], b1[nf][1], bBase + PLANE + (uint32_t)(nf * 8) * ARS + koff);

            // h0*h0 and h0*h1
#pragma unroll
            for (int mf = 0; mf < 4; mf++)
#pragma unroll
                for (int nf = 0; nf < 4; nf++) {
                    MMA16816(c[mf][nf][0], c[mf][nf][1], c[mf][nf][2], c[mf][nf][3],
                             a[mf][0], a[mf][1], a[mf][2], a[mf][3], b0[nf][0], b0[nf][1]);
                    MMA16816(c[mf][nf][0], c[mf][nf][1], c[mf][nf][2], c[mf][nf][3],
                             a[mf][0], a[mf][1], a[mf][2], a[mf][3], b1[nf][0], b1[nf][1]);
                }
            // h1*h0
#pragma unroll
            for (int mf = 0; mf < 4; mf++)
                LDSM_X4(a[mf][0], a[mf][1], a[mf][2], a[mf][3],
                        aP1 + (uint32_t)(mf * 16) * ARS + koff);
#pragma unroll
            for (int mf = 0; mf < 4; mf++)
#pragma unroll
                for (int nf = 0; nf < 4; nf++)
                    MMA16816(c[mf][nf][0], c[mf][nf][1], c[mf][nf][2], c[mf][nf][3],
                             a[mf][0], a[mf][1], a[mf][2], a[mf][3], b0[nf][0], b0[nf][1]);
        }

        // ---- epilogue: gated dump of flagged 32-col row segments ----
#pragma unroll
        for (int mf = 0; mf < 4; mf++) {
            const int r0 = wm * 64 + mf * 16 + g;
            float m0 = fmaxf(fmaxf(c[mf][0][0], c[mf][0][1]), fmaxf(c[mf][1][0], c[mf][1][1]));
            m0 = fmaxf(m0, fmaxf(fmaxf(c[mf][2][0], c[mf][2][1]), fmaxf(c[mf][3][0], c[mf][3][1])));
            float m1 = fmaxf(fmaxf(c[mf][0][2], c[mf][0][3]), fmaxf(c[mf][1][2], c[mf][1][3]));
            m1 = fmaxf(m1, fmaxf(fmaxf(c[mf][2][2], c[mf][2][3]), fmaxf(c[mf][3][2], c[mf][3][3])));
            m0 = fmaxf(m0, __shfl_xor_sync(0xffffffffu, m0, 1));
            m0 = fmaxf(m0, __shfl_xor_sync(0xffffffffu, m0, 2));
            m1 = fmaxf(m1, __shfl_xor_sync(0xffffffffu, m1, 1));
            m1 = fmaxf(m1, __shfl_xor_sync(0xffffffffu, m1, 2));
            if (m0 > thr[r0]) {
#pragma unroll
                for (int nf = 0; nf < 4; nf++) {
                    float2 v; v.x = c[mf][nf][0]; v.y = c[mf][nf][1];
                    *reinterpret_cast<float2*>(&ssim[r0 * 132 + wn * 32 + nf * 8 + 2 * tg]) = v;
                }
                if (tg == 0) flags[r0 * 4 + wn] = 1;
            }
            if (m1 > thr[r0 + 8]) {
#pragma unroll
                for (int nf = 0; nf < 4; nf++) {
                    float2 v; v.x = c[mf][nf][2]; v.y = c[mf][nf][3];
                    *reinterpret_cast<float2*>(&ssim[(r0 + 8) * 132 + wn * 32 + nf * 8 + 2 * tg]) = v;
                }
                if (tg == 0) flags[(r0 + 8) * 4 + wn] = 1;
            }
        }
        __syncthreads();   // dumps+flags visible; B buf free

        // ---- scan (lanes 0-15) + next B tile load (lanes 16-31) ----
        if (l < 16) {
            const int row = wid * 16 + l;
            uint32_t fw = flagw[row];
            if (fw) {
                float* tv = &tval[row * KSEL];
                int*   ti = &tidx[row * KSEL];
                const float* srow = &ssim[row * 132];
                const int kbase = kt * TN;
#pragma unroll 1
                for (int seg = 0; seg < 4; seg++) {
                    if (!((fw >> (seg * 8)) & 0xff)) continue;
#pragma unroll 1
                    for (int q4 = 0; q4 < 8; q4++) {
                        float4 v = *reinterpret_cast<const float4*>(&srow[seg * 32 + q4 * 4]);
                        float vv[4] = {v.x, v.y, v.z, v.w};
#pragma unroll
                        for (int u = 0; u < 4; u++) {
                            float val = vv[u];
                            if (val > tv[KSEL - 1]) {
                                int j = KSEL - 1;
                                while (j > 0 && tv[j - 1] < val) {   // strict: lower index wins
                                    tv[j] = tv[j - 1]; ti[j] = ti[j - 1]; j--;
                                }
                                tv[j] = val; ti[j] = kbase + seg * 32 + q4 * 4 + u;
                            }
                        }
                    }
                }
                thr[row] = tv[KSEL - 1];
                flagw[row] = 0u;
            }
        } else if (kt + 1 < NKT) {
            const int lt = wid * 16 + (l - 16);    // 0..127
            const size_t krow = (size_t)(b * NPIX + (kt + 1) * TN) * RCH;
            char* bufd = smc + B_OFF + ((kt + 1) & 1) * 2 * PLANE;
#pragma unroll
            for (int pl = 0; pl < 2; pl++) {
                const uint4* src = reinterpret_cast<const uint4*>(&g_hs[pl][krow]);
                char* dst = bufd + pl * PLANE;
                for (int e = lt; e < 1024; e += 128) {
                    int i = e >> 3, j = e & 7;
                    *reinterpret_cast<uint4*>(dst + i * ARS + j * 16) = src[e];
                }
            }
        }
        __syncthreads();
    }

    if (l < 16) {
        const int row = wid * 16 + l;
        int* dst = &g_topidx[(size_t)(b * NPIX + q0 + row) * KSEL];
#pragma unroll
        for (int j = 0; j < KSEL; j++) dst[j] = tidx[row * KSEL + j];
    }
}

// ---------------------------------------------------------------------------
// K3: corr = mean of 16 gathered nf rows; out = x + w_proj @ corr
// ---------------------------------------------------------------------------
#define SQS 68
__global__ __launch_bounds__(256) void k3_gather_proj(
    const float* __restrict__ x, const float* __restrict__ w_proj,
    float* __restrict__ out)
{
    extern __shared__ float sm[];
    float* swp   = sm;
    float* scorr = swp + CH * RCH;
    int*   sidx  = reinterpret_cast<int*>(scorr + 64 * SQS);

    const int tid = threadIdx.x;
    const int b   = blockIdx.y;
    const int n0  = blockIdx.x * 64;

    for (int i = tid; i < CH * RCH; i += 256) swp[i] = w_proj[i];
    for (int i = tid; i < 64 * KSEL; i += 256)
        sidx[i] = g_topidx[(size_t)(b * NPIX + n0) * KSEL + i];
    __syncthreads();

    for (int e = tid; e < 64 * RCH; e += 256) {
        int nl = e >> 6, r = e & 63;
        const int* ip = &sidx[nl * KSEL];
        float s = 0.f;
#pragma unroll
        for (int j = 0; j < KSEL; j++)
            s += g_nf[((size_t)b * NPIX + ip[j]) * RCH + r];
        scorr[nl * SQS + r] = s * (1.f / 16.f);
    }
    __syncthreads();

    const int nl = tid & 63;
    const int cq = tid >> 6;
    float creg[RCH];
#pragma unroll
    for (int r4 = 0; r4 < RCH / 4; r4++) {
        float4 v = *reinterpret_cast<const float4*>(&scorr[nl * SQS + r4 * 4]);
        creg[r4*4+0] = v.x; creg[r4*4+1] = v.y; creg[r4*4+2] = v.z; creg[r4*4+3] = v.w;
    }

    const float* xrow = x   + (size_t)b * CH * NPIX + n0 + nl;
    float*       orow = out + (size_t)b * CH * NPIX + n0 + nl;
    for (int cc = 0; cc < 64; cc++) {
        const int c = cq * 64 + cc;
        float accv = 0.f;
        const float4* wrow = reinterpret_cast<const float4*>(&swp[c * RCH]);
#pragma unroll
        for (int r4 = 0; r4 < RCH / 4; r4++) {
            float4 wv = wrow[r4];
            accv += wv.x * creg[r4*4+0] + wv.y * creg[r4*4+1]
                  + wv.z * creg[r4*4+2] + wv.w * creg[r4*4+3];
        }
        orow[(size_t)c * NPIX] = xrow[(size_t)c * NPIX] + accv;
    }
}

// ---------------------------------------------------------------------------
extern "C" void kernel_launch(void* const* d_in, const int* in_sizes, int n_in,
                              void* d_out, int out_size)
{
    const float* x        = (const float*)d_in[0];
    const float* w_reduce = (const float*)d_in[1];
    const float* w_proj   = (const float*)d_in[2];
    float*       out      = (float*)d_out;

    const int smem1 = (CH * WSMS + 256) * 4;
    const int smem2 = SMEM_K2;                                   // ~196 KB
    const int smem3 = CH * RCH * 4 + 64 * SQS * 4 + 64 * KSEL * 4;

    cudaFuncSetAttribute(k1_reduce_norm, cudaFuncAttributeMaxDynamicSharedMemorySize, smem1);
    cudaFuncSetAttribute(k2_sim_topk,    cudaFuncAttributeMaxDynamicSharedMemorySize, smem2);
    cudaFuncSetAttribute(k3_gather_proj, cudaFuncAttributeMaxDynamicSharedMemorySize, smem3);

    k1_reduce_norm<<<(BATCH * NPIX) / 64, 256, smem1>>>(x, w_reduce);
    k2_sim_topk<<<dim3(NPIX / TM, BATCH), 256, smem2>>>();
    k3_gather_proj<<<dim3(NPIX / 64, BATCH), 256, smem3>>>(x, w_proj, out);
}